// round 4
// baseline (speedup 1.0000x reference)
#include <cuda_runtime.h>
#include <math.h>

#define R_ 8
#define N_ 4096
#define F_ 256
#define B_ 16384

// Scratch (device globals — no allocation allowed in kernel_launch)
__device__ float g_T1[(size_t)R_ * N_ * F_];   // 32 MB: H@W^T per r, later P = H2@M[r]
__device__ float g_T2[(size_t)R_ * N_ * F_];   // 32 MB: A[r] @ T1[r]
__device__ float g_H1[(size_t)N_ * F_];        // 4 MB
__device__ float g_H2[(size_t)N_ * F_];        // 4 MB

typedef unsigned long long ull;

__device__ __forceinline__ ull ffma2(ull a, ull b, ull c) {
    ull d;
    asm("fma.rn.f32x2 %0, %1, %2, %3;" : "=l"(d) : "l"(a), "l"(b), "l"(c));
    return d;
}
__device__ __forceinline__ ull dup2(float x) {
    ull d;
    unsigned xu = __float_as_uint(x);
    asm("mov.b64 %0, {%1, %1};" : "=l"(d) : "r"(xu));
    return d;
}

// C[r][n][o] = sum_k A[r][n][k] * (TRANSB ? B[r][o][k] : B[r][k][o])
// ldc fixed = 256. Tile 128x128, BK=16, 256 threads, 8x8 micro (split 4+4 @64).
template <bool TRANSB>
__global__ __launch_bounds__(256, 2)
void gemm_kernel(const float* __restrict__ Abase, const float* __restrict__ Bbase,
                 float* __restrict__ Cbase, int K, int lda, int ldb,
                 size_t strideA, size_t strideB, size_t strideC)
{
    const int r = blockIdx.z;
    const float* Aop = Abase + (size_t)r * strideA;
    const float* Bop = Bbase + (size_t)r * strideB;
    float*       Cop = Cbase + (size_t)r * strideC;

    const int n0 = blockIdx.y * 128;
    const int o0 = blockIdx.x * 128;

    __shared__ __align__(16) float As[2][16][132];
    __shared__ __align__(16) float Bs[2][16][132];

    const int tid = threadIdx.x;
    const int tx = tid & 15;
    const int ty = tid >> 4;

    ull acc[8][4];
#pragma unroll
    for (int i = 0; i < 8; i++)
#pragma unroll
        for (int j = 0; j < 4; j++) acc[i][j] = 0ull;

    float4 aL[2], bL[2];

    // ---- global->register loads for chunk at k-offset kk ----
    auto ldg_chunk = [&](int kk) {
#pragma unroll
        for (int s = 0; s < 2; s++) {
            int t = tid + s * 256;
            int n = t >> 2, kq = (t & 3) * 4;
            aL[s] = *(const float4*)(Aop + (size_t)(n0 + n) * lda + kk + kq);
        }
        if (!TRANSB) {
#pragma unroll
            for (int s = 0; s < 2; s++) {
                int t = tid + s * 256;
                int k = t >> 5, c4 = (t & 31) * 4;
                bL[s] = *(const float4*)(Bop + (size_t)(kk + k) * ldb + o0 + c4);
            }
        } else {
#pragma unroll
            for (int s = 0; s < 2; s++) {
                int t = tid + s * 256;
                int o = t >> 2, kq = (t & 3) * 4;
                bL[s] = *(const float4*)(Bop + (size_t)(o0 + o) * ldb + kk + kq);
            }
        }
    };

    // ---- register->shared stores into buffer b ----
    auto sts_chunk = [&](int b) {
#pragma unroll
        for (int s = 0; s < 2; s++) {
            int t = tid + s * 256;
            int n = t >> 2, kq = (t & 3) * 4;
            As[b][kq + 0][n] = aL[s].x;
            As[b][kq + 1][n] = aL[s].y;
            As[b][kq + 2][n] = aL[s].z;
            As[b][kq + 3][n] = aL[s].w;
        }
        if (!TRANSB) {
#pragma unroll
            for (int s = 0; s < 2; s++) {
                int t = tid + s * 256;
                int k = t >> 5, c4 = (t & 31) * 4;
                *(float4*)&Bs[b][k][c4] = bL[s];
            }
        } else {
#pragma unroll
            for (int s = 0; s < 2; s++) {
                int t = tid + s * 256;
                int o = t >> 2, kq = (t & 3) * 4;
                Bs[b][kq + 0][o] = bL[s].x;
                Bs[b][kq + 1][o] = bL[s].y;
                Bs[b][kq + 2][o] = bL[s].z;
                Bs[b][kq + 3][o] = bL[s].w;
            }
        }
    };

    // ---- compute one 16-deep chunk from buffer b ----
    auto compute_chunk = [&](int b) {
#pragma unroll
        for (int k = 0; k < 16; k++) {
            float4 a0 = *(const float4*)&As[b][k][ty * 4];
            float4 a1 = *(const float4*)&As[b][k][64 + ty * 4];
            ulonglong2 bq0 = *(const ulonglong2*)&Bs[b][k][tx * 4];
            ulonglong2 bq1 = *(const ulonglong2*)&Bs[b][k][64 + tx * 4];
            ull b0 = bq0.x, b1 = bq0.y, b2 = bq1.x, b3 = bq1.y;

            const float a0v[4] = {a0.x, a0.y, a0.z, a0.w};
            const float a1v[4] = {a1.x, a1.y, a1.z, a1.w};
#pragma unroll
            for (int i = 0; i < 4; i++) {
                ull ad = dup2(a0v[i]);
                acc[i][0] = ffma2(ad, b0, acc[i][0]);
                acc[i][1] = ffma2(ad, b1, acc[i][1]);
                acc[i][2] = ffma2(ad, b2, acc[i][2]);
                acc[i][3] = ffma2(ad, b3, acc[i][3]);
            }
#pragma unroll
            for (int i = 0; i < 4; i++) {
                ull ad = dup2(a1v[i]);
                acc[4 + i][0] = ffma2(ad, b0, acc[4 + i][0]);
                acc[4 + i][1] = ffma2(ad, b1, acc[4 + i][1]);
                acc[4 + i][2] = ffma2(ad, b2, acc[4 + i][2]);
                acc[4 + i][3] = ffma2(ad, b3, acc[4 + i][3]);
            }
        }
    };

    // prologue
    ldg_chunk(0);
    sts_chunk(0);
    __syncthreads();

    int buf = 0;
    for (int kk = 16; kk < K; kk += 16) {
        ldg_chunk(kk);          // prefetch next chunk (hides DRAM latency)
        compute_chunk(buf);     // compute current chunk
        sts_chunk(buf ^ 1);     // stage next chunk (other buffer: safe)
        __syncthreads();
        buf ^= 1;
    }
    compute_chunk(buf);

    // epilogue: store 128x128 tile
#pragma unroll
    for (int i = 0; i < 8; i++) {
        int row = n0 + ((i < 4) ? (ty * 4 + i) : (64 + ty * 4 + (i - 4)));
        float* cp = Cop + (size_t)row * F_ + o0;
        ulonglong2 v0, v1;
        v0.x = acc[i][0]; v0.y = acc[i][1];
        v1.x = acc[i][2]; v1.y = acc[i][3];
        *(ulonglong2*)(cp + tx * 4) = v0;
        *(ulonglong2*)(cp + 64 + tx * 4) = v1;
    }
}

// Hout[n,o] = sum_r c[r,n] * T2[r,n,o]
__global__ void reduce_kernel(const float* __restrict__ c, float* __restrict__ Hout)
{
    int idx = blockIdx.x * 256 + threadIdx.x;   // over N*F
    int n = idx >> 8;                           // F = 256
    float s = 0.f;
#pragma unroll
    for (int r = 0; r < R_; r++)
        s = fmaf(c[r * N_ + n], g_T2[(size_t)r * N_ * F_ + idx], s);
    Hout[idx] = s;
}

// out[b] = sigmoid( P[rel_b][e1_b] . H2[e2_b] ), P lives in g_T1
__global__ void score_kernel(const int* __restrict__ e1, const int* __restrict__ rel,
                             const int* __restrict__ e2, float* __restrict__ out)
{
    int b = blockIdx.x * 8 + (threadIdx.x >> 5);
    int lane = threadIdx.x & 31;
    const float* p = g_T1 + ((size_t)rel[b] * N_ + e1[b]) * F_;
    const float* h = g_H2 + (size_t)e2[b] * F_;
    float s = 0.f;
#pragma unroll
    for (int i = 0; i < 2; i++) {               // 2 * 32 lanes * float4 = 256
        float4 pv = *(const float4*)(p + (lane + i * 32) * 4);
        float4 hv = *(const float4*)(h + (lane + i * 32) * 4);
        s += pv.x * hv.x + pv.y * hv.y + pv.z * hv.z + pv.w * hv.w;
    }
#pragma unroll
    for (int o = 16; o; o >>= 1) s += __shfl_xor_sync(0xffffffffu, s, o);
    if (lane == 0) out[b] = 1.f / (1.f + expf(-s));   // saturates to exact 0/1 at |s|~1e13
}

extern "C" void kernel_launch(void* const* d_in, const int* in_sizes, int n_in,
                              void* d_out, int out_size)
{
    const float* A   = (const float*)d_in[0];  // [R,N,N]
    const float* X   = (const float*)d_in[1];  // [N,F]
    const float* c   = (const float*)d_in[2];  // [R,N,1]
    const float* W1  = (const float*)d_in[3];  // [R,F,F]
    const float* W2  = (const float*)d_in[4];  // [R,F,F]
    const float* M   = (const float*)d_in[5];  // [R,F,F]
    const int*   e1  = (const int*)d_in[6];
    const int*   rel = (const int*)d_in[7];
    const int*   e2  = (const int*)d_in[8];
    float* out = (float*)d_out;

    float *T1, *T2, *H1, *H2;
    cudaGetSymbolAddress((void**)&T1, g_T1);
    cudaGetSymbolAddress((void**)&T2, g_T2);
    cudaGetSymbolAddress((void**)&H1, g_H1);
    cudaGetSymbolAddress((void**)&H2, g_H2);

    dim3 blk(256);
    dim3 grid(2, 32, 8);   // (o-tiles, n-tiles, r)

    const size_t sNN = (size_t)N_ * N_;
    const size_t sNF = (size_t)N_ * F_;
    const size_t sFF = (size_t)F_ * F_;

    // ---- layer 1: H1 = sum_r c[r] o ( A[r] @ (X @ W1[r]^T) ) ----
    gemm_kernel<true ><<<grid, blk>>>(X,  W1, T1, F_, F_,  F_, 0,   sFF, sNF);
    gemm_kernel<false><<<grid, blk>>>(A,  T1, T2, N_, N_,  F_, sNN, sNF, sNF);
    reduce_kernel<<<(N_ * F_) / 256, blk>>>(c, H1);

    // ---- layer 2 ----
    gemm_kernel<true ><<<grid, blk>>>(H1, W2, T1, F_, F_,  F_, 0,   sFF, sNF);
    gemm_kernel<false><<<grid, blk>>>(A,  T1, T2, N_, N_,  F_, sNN, sNF, sNF);
    reduce_kernel<<<(N_ * F_) / 256, blk>>>(c, H2);

    // ---- scoring: P[r] = H2 @ M[r], then gathered dot + sigmoid ----
    gemm_kernel<false><<<grid, blk>>>(H2, M,  T1, F_, F_,  F_, 0,   sFF, sNF);
    score_kernel<<<B_ / 8, blk>>>(e1, rel, e2, out);
}

// round 5
// speedup vs baseline: 1.0008x; 1.0008x over previous
#include <cuda_runtime.h>
#include <math.h>

#define R_ 8
#define N_ 4096
#define F_ 256
#define B_ 16384

// Scratch (device globals — no allocation allowed in kernel_launch)
__device__ float g_T1[(size_t)R_ * N_ * F_];   // 32 MB: H@W^T per r, later P = H2@M[r]
__device__ float g_T2[(size_t)R_ * N_ * F_];   // 32 MB: A[r] @ T1[r]
__device__ float g_H1[(size_t)N_ * F_];        // 4 MB
__device__ float g_H2[(size_t)N_ * F_];        // 4 MB

typedef unsigned long long ull;

__device__ __forceinline__ ull ffma2(ull a, ull b, ull c) {
    ull d;
    asm("fma.rn.f32x2 %0, %1, %2, %3;" : "=l"(d) : "l"(a), "l"(b), "l"(c));
    return d;
}
__device__ __forceinline__ ull dup2(float x) {
    ull d;
    unsigned xu = __float_as_uint(x);
    asm("mov.b64 %0, {%1, %1};" : "=l"(d) : "r"(xu));
    return d;
}

// C[r][n][o] = sum_k A[r][n][k] * (TRANSB ? B[r][o][k] : B[r][k][o])
// ldc fixed = 256. Tile 128x128, BK=16, 256 threads, 8x8 micro (split 4+4 @64).
template <bool TRANSB>
__global__ __launch_bounds__(256, 2)
void gemm_kernel(const float* __restrict__ Abase, const float* __restrict__ Bbase,
                 float* __restrict__ Cbase, int K, int lda, int ldb,
                 size_t strideA, size_t strideB, size_t strideC)
{
    const int r = blockIdx.z;
    const float* Aop = Abase + (size_t)r * strideA;
    const float* Bop = Bbase + (size_t)r * strideB;
    float*       Cop = Cbase + (size_t)r * strideC;

    const int n0 = blockIdx.y * 128;
    const int o0 = blockIdx.x * 128;

    __shared__ __align__(16) float As[2][16][132];
    __shared__ __align__(16) float Bs[2][16][132];

    const int tid = threadIdx.x;
    const int tx = tid & 15;
    const int ty = tid >> 4;

    ull acc[8][4];
#pragma unroll
    for (int i = 0; i < 8; i++)
#pragma unroll
        for (int j = 0; j < 4; j++) acc[i][j] = 0ull;

    float4 aL[2], bL[2];

    // ---- global->register loads for chunk at k-offset kk ----
    auto ldg_chunk = [&](int kk) {
#pragma unroll
        for (int s = 0; s < 2; s++) {
            int t = tid + s * 256;
            int n = t >> 2, kq = (t & 3) * 4;
            aL[s] = *(const float4*)(Aop + (size_t)(n0 + n) * lda + kk + kq);
        }
        if (!TRANSB) {
#pragma unroll
            for (int s = 0; s < 2; s++) {
                int t = tid + s * 256;
                int k = t >> 5, c4 = (t & 31) * 4;
                bL[s] = *(const float4*)(Bop + (size_t)(kk + k) * ldb + o0 + c4);
            }
        } else {
#pragma unroll
            for (int s = 0; s < 2; s++) {
                int t = tid + s * 256;
                int o = t >> 2, kq = (t & 3) * 4;
                bL[s] = *(const float4*)(Bop + (size_t)(o0 + o) * ldb + kk + kq);
            }
        }
    };

    // ---- register->shared stores into buffer b ----
    auto sts_chunk = [&](int b) {
#pragma unroll
        for (int s = 0; s < 2; s++) {
            int t = tid + s * 256;
            int n = t >> 2, kq = (t & 3) * 4;
            As[b][kq + 0][n] = aL[s].x;
            As[b][kq + 1][n] = aL[s].y;
            As[b][kq + 2][n] = aL[s].z;
            As[b][kq + 3][n] = aL[s].w;
        }
        if (!TRANSB) {
#pragma unroll
            for (int s = 0; s < 2; s++) {
                int t = tid + s * 256;
                int k = t >> 5, c4 = (t & 31) * 4;
                *(float4*)&Bs[b][k][c4] = bL[s];
            }
        } else {
#pragma unroll
            for (int s = 0; s < 2; s++) {
                int t = tid + s * 256;
                int o = t >> 2, kq = (t & 3) * 4;
                Bs[b][kq + 0][o] = bL[s].x;
                Bs[b][kq + 1][o] = bL[s].y;
                Bs[b][kq + 2][o] = bL[s].z;
                Bs[b][kq + 3][o] = bL[s].w;
            }
        }
    };

    // ---- compute one 16-deep chunk from buffer b ----
    auto compute_chunk = [&](int b) {
#pragma unroll
        for (int k = 0; k < 16; k++) {
            float4 a0 = *(const float4*)&As[b][k][ty * 4];
            float4 a1 = *(const float4*)&As[b][k][64 + ty * 4];
            ulonglong2 bq0 = *(const ulonglong2*)&Bs[b][k][tx * 4];
            ulonglong2 bq1 = *(const ulonglong2*)&Bs[b][k][64 + tx * 4];
            ull b0 = bq0.x, b1 = bq0.y, b2 = bq1.x, b3 = bq1.y;

            const float a0v[4] = {a0.x, a0.y, a0.z, a0.w};
            const float a1v[4] = {a1.x, a1.y, a1.z, a1.w};
#pragma unroll
            for (int i = 0; i < 4; i++) {
                ull ad = dup2(a0v[i]);
                acc[i][0] = ffma2(ad, b0, acc[i][0]);
                acc[i][1] = ffma2(ad, b1, acc[i][1]);
                acc[i][2] = ffma2(ad, b2, acc[i][2]);
                acc[i][3] = ffma2(ad, b3, acc[i][3]);
            }
#pragma unroll
            for (int i = 0; i < 4; i++) {
                ull ad = dup2(a1v[i]);
                acc[4 + i][0] = ffma2(ad, b0, acc[4 + i][0]);
                acc[4 + i][1] = ffma2(ad, b1, acc[4 + i][1]);
                acc[4 + i][2] = ffma2(ad, b2, acc[4 + i][2]);
                acc[4 + i][3] = ffma2(ad, b3, acc[4 + i][3]);
            }
        }
    };

    // prologue
    ldg_chunk(0);
    sts_chunk(0);
    __syncthreads();

    int buf = 0;
    for (int kk = 16; kk < K; kk += 16) {
        ldg_chunk(kk);          // prefetch next chunk (hides DRAM latency)
        compute_chunk(buf);     // compute current chunk
        sts_chunk(buf ^ 1);     // stage next chunk (other buffer: safe)
        __syncthreads();
        buf ^= 1;
    }
    compute_chunk(buf);

    // epilogue: store 128x128 tile
#pragma unroll
    for (int i = 0; i < 8; i++) {
        int row = n0 + ((i < 4) ? (ty * 4 + i) : (64 + ty * 4 + (i - 4)));
        float* cp = Cop + (size_t)row * F_ + o0;
        ulonglong2 v0, v1;
        v0.x = acc[i][0]; v0.y = acc[i][1];
        v1.x = acc[i][2]; v1.y = acc[i][3];
        *(ulonglong2*)(cp + tx * 4) = v0;
        *(ulonglong2*)(cp + 64 + tx * 4) = v1;
    }
}

// Hout[n,o] = sum_r c[r,n] * T2[r,n,o]
__global__ void reduce_kernel(const float* __restrict__ c, float* __restrict__ Hout)
{
    int idx = blockIdx.x * 256 + threadIdx.x;   // over N*F
    int n = idx >> 8;                           // F = 256
    float s = 0.f;
#pragma unroll
    for (int r = 0; r < R_; r++)
        s = fmaf(c[r * N_ + n], g_T2[(size_t)r * N_ * F_ + idx], s);
    Hout[idx] = s;
}

// out[b] = sigmoid( P[rel_b][e1_b] . H2[e2_b] ), P lives in g_T1
__global__ void score_kernel(const int* __restrict__ e1, const int* __restrict__ rel,
                             const int* __restrict__ e2, float* __restrict__ out)
{
    int b = blockIdx.x * 8 + (threadIdx.x >> 5);
    int lane = threadIdx.x & 31;
    const float* p = g_T1 + ((size_t)rel[b] * N_ + e1[b]) * F_;
    const float* h = g_H2 + (size_t)e2[b] * F_;
    float s = 0.f;
#pragma unroll
    for (int i = 0; i < 2; i++) {               // 2 * 32 lanes * float4 = 256
        float4 pv = *(const float4*)(p + (lane + i * 32) * 4);
        float4 hv = *(const float4*)(h + (lane + i * 32) * 4);
        s += pv.x * hv.x + pv.y * hv.y + pv.z * hv.z + pv.w * hv.w;
    }
#pragma unroll
    for (int o = 16; o; o >>= 1) s += __shfl_xor_sync(0xffffffffu, s, o);
    if (lane == 0) out[b] = 1.f / (1.f + expf(-s));   // saturates to exact 0/1 at |s|~1e13
}

extern "C" void kernel_launch(void* const* d_in, const int* in_sizes, int n_in,
                              void* d_out, int out_size)
{
    const float* A   = (const float*)d_in[0];  // [R,N,N]
    const float* X   = (const float*)d_in[1];  // [N,F]
    const float* c   = (const float*)d_in[2];  // [R,N,1]
    const float* W1  = (const float*)d_in[3];  // [R,F,F]
    const float* W2  = (const float*)d_in[4];  // [R,F,F]
    const float* M   = (const float*)d_in[5];  // [R,F,F]
    const int*   e1  = (const int*)d_in[6];
    const int*   rel = (const int*)d_in[7];
    const int*   e2  = (const int*)d_in[8];
    float* out = (float*)d_out;

    float *T1, *T2, *H1, *H2;
    cudaGetSymbolAddress((void**)&T1, g_T1);
    cudaGetSymbolAddress((void**)&T2, g_T2);
    cudaGetSymbolAddress((void**)&H1, g_H1);
    cudaGetSymbolAddress((void**)&H2, g_H2);

    dim3 blk(256);
    dim3 grid(2, 32, 8);   // (o-tiles, n-tiles, r)

    const size_t sNN = (size_t)N_ * N_;
    const size_t sNF = (size_t)N_ * F_;
    const size_t sFF = (size_t)F_ * F_;

    // ---- layer 1: H1 = sum_r c[r] o ( A[r] @ (X @ W1[r]^T) ) ----
    gemm_kernel<true ><<<grid, blk>>>(X,  W1, T1, F_, F_,  F_, 0,   sFF, sNF);
    gemm_kernel<false><<<grid, blk>>>(A,  T1, T2, N_, N_,  F_, sNN, sNF, sNF);
    reduce_kernel<<<(N_ * F_) / 256, blk>>>(c, H1);

    // ---- layer 2 ----
    gemm_kernel<true ><<<grid, blk>>>(H1, W2, T1, F_, F_,  F_, 0,   sFF, sNF);
    gemm_kernel<false><<<grid, blk>>>(A,  T1, T2, N_, N_,  F_, sNN, sNF, sNF);
    reduce_kernel<<<(N_ * F_) / 256, blk>>>(c, H2);

    // ---- scoring: P[r] = H2 @ M[r], then gathered dot + sigmoid ----
    gemm_kernel<false><<<grid, blk>>>(H2, M,  T1, F_, F_,  F_, 0,   sFF, sNF);
    score_kernel<<<B_ / 8, blk>>>(e1, rel, e2, out);
}